// round 1
// baseline (speedup 1.0000x reference)
#include <cuda_runtime.h>

#define B_   32
#define C_   128
#define H_   36
#define W_   100
#define K_   9
#define PAD_ 4

#define CI_T 16
#define VLP  108   // padded W: 4 + 100 + 4
#define HLP  44    // padded H: 4 + 36 + 4

// Transposed weights: [pass][ci*9*128 + k*128 + co]
__device__ float g_wtT[4][C_ * K_ * C_];

__global__ void transpose_weights(const float* __restrict__ w0,
                                  const float* __restrict__ w1,
                                  const float* __restrict__ w2,
                                  const float* __restrict__ w3) {
    const int per = C_ * C_ * K_;
    const int total = 4 * per;
    for (int idx = blockIdx.x * blockDim.x + threadIdx.x; idx < total;
         idx += gridDim.x * blockDim.x) {
        int p = idx / per;
        int r = idx - p * per;
        int ci = r / (K_ * C_);
        int k  = (r / C_) % K_;
        int co = r % C_;
        const float* src = (p == 0) ? w0 : (p == 1) ? w1 : (p == 2) ? w2 : w3;
        g_wtT[p][r] = src[(co * C_ + ci) * K_ + k];
    }
}

// ---------------------------------------------------------------------------
// Vertical step: out[b,co,s_cur,w] += relu( sum_{ci,k} W[co,ci,k] *
//                                           out[b,ci,s_prev,w+k-4] )
// Grid: (B_, 4 co-blocks of 32). Block: 256 threads (200 compute).
// Thread tile: 4 co x 4 w.
// ---------------------------------------------------------------------------
__global__ __launch_bounds__(256) void step_v(float* __restrict__ buf,
                                              int pass, int s_prev, int s_cur) {
    __shared__ __align__(16) float p[64 * VLP];        // 27648 B
    __shared__ __align__(16) float ws[CI_T * K_ * 32]; // 18432 B

    const float* __restrict__ wtT = g_wtT[pass];

    const int b = blockIdx.x;
    const int co_base = blockIdx.y * 32;
    const int tid = threadIdx.x;
    const int tw = tid % 25;   // w group (4 w each)
    const int tc = tid / 25;   // co group (4 co each), valid for tid<200
    const bool active = tid < 200;

    float acc[4][4];
#pragma unroll
    for (int i = 0; i < 4; i++)
#pragma unroll
        for (int j = 0; j < 4; j++) acc[i][j] = 0.f;

    const float* prow_g = buf + (b * C_) * (H_ * W_) + s_prev * W_;

    for (int half = 0; half < 2; half++) {
        __syncthreads();
        // Stage 64 ci of the previous row, zero-padded to 108 cols.
        for (int i = tid; i < 64 * VLP; i += 256) {
            int ci_l = i / VLP;
            int wp = i - ci_l * VLP;
            float v = 0.f;
            if (wp >= PAD_ && wp < PAD_ + W_)
                v = prow_g[(half * 64 + ci_l) * (H_ * W_) + (wp - PAD_)];
            p[i] = v;
        }
        for (int c8 = 0; c8 < 4; c8++) {
            const int ci0 = half * 64 + c8 * CI_T;
            __syncthreads();
            // Stage weight chunk [CI_T][9][32] (coalesced float4).
            for (int j4 = tid * 4; j4 < CI_T * K_ * 32; j4 += 256 * 4) {
                int ci_l = j4 / (K_ * 32);
                int rem = j4 - ci_l * (K_ * 32);
                int k = rem / 32;
                int col = rem - k * 32;
                float4 v = *(const float4*)&wtT[(ci0 + ci_l) * (K_ * C_) +
                                                k * C_ + co_base + col];
                *(float4*)&ws[j4] = v;
            }
            __syncthreads();
            if (active) {
#pragma unroll
                for (int ci_l = 0; ci_l < CI_T; ci_l++) {
                    const float* prow = &p[(c8 * CI_T + ci_l) * VLP + tw * 4];
                    float pv[12];
                    float4 a0 = *(const float4*)(prow);
                    float4 a1 = *(const float4*)(prow + 4);
                    float4 a2 = *(const float4*)(prow + 8);
                    pv[0] = a0.x; pv[1] = a0.y; pv[2]  = a0.z; pv[3]  = a0.w;
                    pv[4] = a1.x; pv[5] = a1.y; pv[6]  = a1.z; pv[7]  = a1.w;
                    pv[8] = a2.x; pv[9] = a2.y; pv[10] = a2.z; pv[11] = a2.w;
#pragma unroll
                    for (int k = 0; k < K_; k++) {
                        float4 wv = *(const float4*)&ws[(ci_l * K_ + k) * 32 + tc * 4];
#pragma unroll
                        for (int wwi = 0; wwi < 4; wwi++) {
                            float pe = pv[k + wwi];
                            acc[0][wwi] += wv.x * pe;
                            acc[1][wwi] += wv.y * pe;
                            acc[2][wwi] += wv.z * pe;
                            acc[3][wwi] += wv.w * pe;
                        }
                    }
                }
            }
        }
    }
    if (active) {
#pragma unroll
        for (int cc = 0; cc < 4; cc++) {
            int co = co_base + tc * 4 + cc;
            float4* orow = (float4*)(buf + ((b * C_ + co) * H_ + s_cur) * W_ + tw * 4);
            float4 o = *orow;
            o.x += fmaxf(acc[cc][0], 0.f);
            o.y += fmaxf(acc[cc][1], 0.f);
            o.z += fmaxf(acc[cc][2], 0.f);
            o.w += fmaxf(acc[cc][3], 0.f);
            *orow = o;
        }
    }
}

// ---------------------------------------------------------------------------
// Horizontal step: out[b,co,h,s_cur] += relu( sum_{ci,k} W[co,ci,k] *
//                                             out[b,ci,h+k-4,s_prev] )
// Grid: (B_, 4 co-blocks of 32). Block: 144 threads (8 co-grp x 18 h-grp).
// Thread tile: 4 co x 2 h.
// ---------------------------------------------------------------------------
__global__ __launch_bounds__(144) void step_h(float* __restrict__ buf,
                                              int pass, int s_prev, int s_cur) {
    __shared__ __align__(16) float pc[C_ * HLP];       // 22528 B
    __shared__ __align__(16) float ws[CI_T * K_ * 32]; // 18432 B

    const float* __restrict__ wtT = g_wtT[pass];

    const int b = blockIdx.x;
    const int co_base = blockIdx.y * 32;
    const int tid = threadIdx.x;
    const int tc = tid / 18;  // 0..7
    const int th = tid % 18;  // 0..17

    float acc[4][2];
#pragma unroll
    for (int i = 0; i < 4; i++) { acc[i][0] = 0.f; acc[i][1] = 0.f; }

    // Stage the previous column (all 128 ci), zero-padded to 44 rows.
    for (int i = tid; i < C_ * HLP; i += 144) {
        int ci = i / HLP;
        int hp = i - ci * HLP;
        float v = 0.f;
        if (hp >= PAD_ && hp < PAD_ + H_)
            v = buf[((b * C_ + ci) * H_ + (hp - PAD_)) * W_ + s_prev];
        pc[i] = v;
    }

    for (int c8 = 0; c8 < 8; c8++) {
        const int ci0 = c8 * CI_T;
        __syncthreads();
        for (int j4 = tid * 4; j4 < CI_T * K_ * 32; j4 += 144 * 4) {
            int ci_l = j4 / (K_ * 32);
            int rem = j4 - ci_l * (K_ * 32);
            int k = rem / 32;
            int col = rem - k * 32;
            float4 v = *(const float4*)&wtT[(ci0 + ci_l) * (K_ * C_) +
                                            k * C_ + co_base + col];
            *(float4*)&ws[j4] = v;
        }
        __syncthreads();
#pragma unroll
        for (int ci_l = 0; ci_l < CI_T; ci_l++) {
            const float* prow = &pc[(ci0 + ci_l) * HLP + th * 2];
            float pv[10];
#pragma unroll
            for (int j = 0; j < 5; j++) {
                float2 t = *(const float2*)(prow + 2 * j);
                pv[2 * j] = t.x; pv[2 * j + 1] = t.y;
            }
#pragma unroll
            for (int k = 0; k < K_; k++) {
                float4 wv = *(const float4*)&ws[(ci_l * K_ + k) * 32 + tc * 4];
#pragma unroll
                for (int hh = 0; hh < 2; hh++) {
                    float pe = pv[k + hh];
                    acc[0][hh] += wv.x * pe;
                    acc[1][hh] += wv.y * pe;
                    acc[2][hh] += wv.z * pe;
                    acc[3][hh] += wv.w * pe;
                }
            }
        }
    }

#pragma unroll
    for (int cc = 0; cc < 4; cc++) {
        int co = co_base + tc * 4 + cc;
#pragma unroll
        for (int hh = 0; hh < 2; hh++) {
            int h = th * 2 + hh;
            int idx = ((b * C_ + co) * H_ + h) * W_ + s_cur;
            float r = acc[cc][hh];
            buf[idx] += fmaxf(r, 0.f);
        }
    }
}

extern "C" void kernel_launch(void* const* d_in, const int* in_sizes, int n_in,
                              void* d_out, int out_size) {
    const float* x    = (const float*)d_in[0];
    const float* w_ud = (const float*)d_in[1];
    const float* w_du = (const float*)d_in[2];
    const float* w_lr = (const float*)d_in[3];
    const float* w_rl = (const float*)d_in[4];
    float* buf = (float*)d_out;

    size_t bytes = (size_t)B_ * C_ * H_ * W_ * sizeof(float);
    cudaMemcpyAsync(buf, x, bytes, cudaMemcpyDeviceToDevice, 0);

    transpose_weights<<<288, 256>>>(w_ud, w_du, w_lr, w_rl);

    dim3 gv(B_, 4);
    dim3 gh(B_, 4);

    // Pass 1: top -> bottom (vertical, w_ud)
    for (int h = 1; h < H_; h++)
        step_v<<<gv, 256>>>(buf, 0, h - 1, h);
    // Pass 2: bottom -> top (vertical, w_du)
    for (int h = H_ - 2; h >= 0; h--)
        step_v<<<gv, 256>>>(buf, 1, h + 1, h);
    // Pass 3: left -> right (horizontal, w_lr)
    for (int w = 1; w < W_; w++)
        step_h<<<gh, 144>>>(buf, 2, w - 1, w);
    // Pass 4: right -> left (horizontal, w_rl)
    for (int w = W_ - 2; w >= 0; w--)
        step_h<<<gh, 144>>>(buf, 3, w + 1, w);
}

// round 6
// speedup vs baseline: 1.5208x; 1.5208x over previous
#include <cuda_runtime.h>

#define B_   32
#define C_   128
#define H_   36
#define W_   100
#define K_   9
#define PAD_ 4

#define VLP  120   // padded W row in smem
#define HLP  48    // padded H row in smem
#define HW_  (H_ * W_)

typedef unsigned long long ull;

// Transposed weights: [pass][ci*9*128 + k*128 + co]
__device__ float g_wtT[4][C_ * K_ * C_];
// Scratch: feature map transposed to [B][C][W][H] for horizontal passes
__device__ float g_bufT[B_ * C_ * W_ * H_];

__device__ __forceinline__ ull pk2(float x) {
    ull r;
    asm("mov.b64 %0, {%1, %1};" : "=l"(r) : "f"(x));
    return r;
}
__device__ __forceinline__ void fma2(ull& d, ull a, ull b) {
    asm("fma.rn.f32x2 %0, %1, %2, %0;" : "+l"(d) : "l"(a), "l"(b));
}
__device__ __forceinline__ float2 unpk(ull v) {
    float2 f;
    asm("mov.b64 {%0, %1}, %2;" : "=f"(f.x), "=f"(f.y) : "l"(v));
    return f;
}
__device__ __forceinline__ void csync() {
    asm volatile("barrier.cluster.arrive.aligned;" ::: "memory");
    asm volatile("barrier.cluster.wait.aligned;" ::: "memory");
}

__global__ void transpose_weights(const float* __restrict__ w0,
                                  const float* __restrict__ w1,
                                  const float* __restrict__ w2,
                                  const float* __restrict__ w3) {
    const int per = C_ * C_ * K_;
    const int total = 4 * per;
    for (int idx = blockIdx.x * blockDim.x + threadIdx.x; idx < total;
         idx += gridDim.x * blockDim.x) {
        int p = idx / per;
        int r = idx - p * per;
        int ci = r / (K_ * C_);
        int k  = (r / C_) % K_;
        int co = r % C_;
        const float* src = (p == 0) ? w0 : (p == 1) ? w1 : (p == 2) ? w2 : w3;
        g_wtT[p][r] = src[(co * C_ + ci) * K_ + k];
    }
}

// ---------------------------------------------------------------------------
// Persistent kernel. Cluster of 4 CTAs = one batch (each CTA owns 32 co).
// Grid (4, 32): blockIdx.x = co-block, blockIdx.y = batch.
// ---------------------------------------------------------------------------
__global__ void __cluster_dims__(4, 1, 1) __launch_bounds__(256, 1)
scnn_persistent(float* __restrict__ buf) {
    extern __shared__ float smem[];
    float* ws = smem;                  // [ci][k][32] : 36864 floats
    float* pr = smem + C_ * K_ * 32;   // row/col buffer: 15360 floats

    const int b = blockIdx.y;
    const int co_base = blockIdx.x * 32;
    const int tid = threadIdx.x;
    const int copair = tid & 15;       // 0..15 -> co pair
    const int sgrp = tid >> 4;         // 0..15 -> spatial group
    const int co_l = copair * 2;

    float* bT = g_bufT;

    for (int pass = 0; pass < 4; pass++) {
        // ---- stage this pass's weight slice [ci][k][32co] into smem ----
        {
            const float* src = g_wtT[pass];
            for (int i = tid; i < C_ * K_ * 8; i += 256) {
                int cik = i >> 3;
                int g = (i & 7) * 4;
                float4 v = *(const float4*)(src + cik * C_ + co_base + g);
                *(float4*)(ws + cik * 32 + g) = v;
            }
        }

        if (pass == 0) {
            // zero smem pads for vertical layout (persist across steps)
            for (int i = tid; i < C_ * VLP; i += 256) {
                int wp = i % VLP;
                if (wp < PAD_ || wp >= PAD_ + W_) pr[i] = 0.f;
            }
        }

        if (pass == 2) {
            __syncthreads();
            // transpose own channel slice: buf[b][c][h][w] -> bT[b][c][w][h]
            for (int c = 0; c < 32; c++) {
                int ch = co_base + c;
                const float* srcp = buf + (size_t)(b * C_ + ch) * HW_;
                for (int i = tid; i < HW_ / 4; i += 256) {
                    float4 v = __ldcg((const float4*)srcp + i);
                    *(float4*)(pr + i * 4) = v;
                }
                __syncthreads();
                float* dstp = bT + (size_t)(b * C_ + ch) * HW_;
                for (int i = tid; i < HW_; i += 256) {
                    int w = i / H_, h = i - w * H_;
                    __stcg(dstp + i, pr[h * W_ + w]);
                }
                __syncthreads();
            }
            // zero smem pads for horizontal layout
            for (int i = tid; i < C_ * HLP; i += 256) {
                int hp = i % HLP;
                if (hp < PAD_ || hp >= PAD_ + H_) pr[i] = 0.f;
            }
            __threadfence();
            csync();
        }
        __syncthreads();  // weights (and pads) staged

        if (pass < 2) {
            // ================= vertical pass =================
            const bool rev = (pass == 1);
            const int wbase = sgrp * 7;
            for (int s = 1; s < H_; s++) {
                const int cur = rev ? (H_ - 1 - s) : s;
                const int prev = rev ? (cur + 1) : (cur - 1);
                const float* rowg = buf + (size_t)b * C_ * HW_ + prev * W_;
                for (int i = tid; i < C_ * 25; i += 256) {
                    int ci = i / 25, q = i - ci * 25;
                    float4 v = __ldcg((const float4*)(rowg + ci * HW_) + q);
                    *(float4*)(pr + ci * VLP + PAD_ + q * 4) = v;
                }
                __syncthreads();

                if (sgrp < 15) {
                    ull acc[7];
#pragma unroll
                    for (int w = 0; w < 7; w++) acc[w] = 0ull;
                    for (int ci = 0; ci < C_; ci++) {
                        // padded origin: out pixel (wbase+w) reads padded
                        // inputs (wbase+w) .. (wbase+w+8); the k-PAD_ shift
                        // is absorbed by the +PAD_ offset used when staging.
                        const float* prp = pr + ci * VLP + wbase;
                        ull pv[15];
#pragma unroll
                        for (int j = 0; j < 15; j++) pv[j] = pk2(prp[j]);
                        const float* wr = ws + ci * (K_ * 32) + co_l;
#pragma unroll
                        for (int k = 0; k < K_; k++) {
                            ull wv = *(const ull*)(wr + k * 32);
#pragma unroll
                            for (int w = 0; w < 7; w++)
                                fma2(acc[w], wv, pv[k + w]);
                        }
                    }
                    float* o0 = buf + ((size_t)(b * C_ + co_base + co_l) * H_ + cur) * W_;
#pragma unroll
                    for (int w = 0; w < 7; w++) {
                        int wg = wbase + w;
                        if (wg < W_) {
                            float2 v = unpk(acc[w]);
                            __stcg(o0 + wg, __ldcg(o0 + wg) + fmaxf(v.x, 0.f));
                            __stcg(o0 + HW_ + wg, __ldcg(o0 + HW_ + wg) + fmaxf(v.y, 0.f));
                        }
                    }
                }
                __threadfence();
                csync();
            }
        } else {
            // ================= horizontal pass (on bT, [b][c][w][h]) =========
            const bool rev = (pass == 3);
            const int hbase = sgrp * 3;
            for (int s = 1; s < W_; s++) {
                const int cur = rev ? (W_ - 1 - s) : s;
                const int prev = rev ? (cur + 1) : (cur - 1);
                const float* colg = bT + (size_t)b * C_ * HW_ + prev * H_;
                for (int i = tid; i < C_ * 9; i += 256) {
                    int ci = i / 9, q = i - ci * 9;
                    float4 v = __ldcg((const float4*)(colg + ci * HW_) + q);
                    *(float4*)(pr + ci * HLP + PAD_ + q * 4) = v;
                }
                __syncthreads();

                if (sgrp < 12) {
                    ull acc[3];
                    acc[0] = acc[1] = acc[2] = 0ull;
                    for (int ci = 0; ci < C_; ci++) {
                        // padded origin (see vertical pass comment)
                        const float* prp = pr + ci * HLP + hbase;
                        ull pv[11];
#pragma unroll
                        for (int j = 0; j < 11; j++) pv[j] = pk2(prp[j]);
                        const float* wr = ws + ci * (K_ * 32) + co_l;
#pragma unroll
                        for (int k = 0; k < K_; k++) {
                            ull wv = *(const ull*)(wr + k * 32);
#pragma unroll
                            for (int h = 0; h < 3; h++)
                                fma2(acc[h], wv, pv[k + h]);
                        }
                    }
                    float* o0 = bT + ((size_t)(b * C_ + co_base + co_l) * W_ + cur) * H_ + hbase;
#pragma unroll
                    for (int h = 0; h < 3; h++) {
                        float2 v = unpk(acc[h]);
                        __stcg(o0 + h, __ldcg(o0 + h) + fmaxf(v.x, 0.f));
                        __stcg(o0 + HW_ + h, __ldcg(o0 + HW_ + h) + fmaxf(v.y, 0.f));
                    }
                }
                __threadfence();
                csync();
            }
        }
        __threadfence();
        csync();  // end of pass

        if (pass == 3) {
            // transpose back: bT[b][c][w][h] -> buf[b][c][h][w]
            for (int c = 0; c < 32; c++) {
                int ch = co_base + c;
                const float* srcp = bT + (size_t)(b * C_ + ch) * HW_;
                for (int i = tid; i < HW_ / 4; i += 256) {
                    float4 v = __ldcg((const float4*)srcp + i);
                    *(float4*)(pr + i * 4) = v;
                }
                __syncthreads();
                float* dstp = buf + (size_t)(b * C_ + ch) * HW_;
                for (int i = tid; i < HW_; i += 256) {
                    int h = i / W_, w = i - h * W_;
                    __stcg(dstp + i, pr[w * H_ + h]);
                }
                __syncthreads();
            }
        }
    }
}

extern "C" void kernel_launch(void* const* d_in, const int* in_sizes, int n_in,
                              void* d_out, int out_size) {
    const float* x    = (const float*)d_in[0];
    const float* w_ud = (const float*)d_in[1];
    const float* w_du = (const float*)d_in[2];
    const float* w_lr = (const float*)d_in[3];
    const float* w_rl = (const float*)d_in[4];
    float* buf = (float*)d_out;

    size_t bytes = (size_t)B_ * C_ * HW_ * sizeof(float);
    cudaMemcpyAsync(buf, x, bytes, cudaMemcpyDeviceToDevice, 0);

    transpose_weights<<<288, 256>>>(w_ud, w_du, w_lr, w_rl);

    const int smem_bytes = (C_ * K_ * 32 + C_ * VLP) * sizeof(float);  // 208896
    cudaFuncSetAttribute(scnn_persistent,
                         cudaFuncAttributeMaxDynamicSharedMemorySize, smem_bytes);

    dim3 grid(4, B_);
    scnn_persistent<<<grid, 256, smem_bytes>>>(buf);
}

// round 8
// speedup vs baseline: 1.8357x; 1.2071x over previous
#include <cuda_runtime.h>

#define B_   32
#define C_   128
#define H_   36
#define W_   100
#define K_   9
#define PAD_ 4

#define VLP  120   // padded W row in smem (4 + 100 + pad to 120)
#define HLP  48    // padded H col in smem (4 + 36 + 8)
#define HW_  (H_ * W_)

typedef unsigned long long ull;

// Transposed weights: [pass][ci*9*128 + k*128 + co]
__device__ float g_wtT[4][C_ * K_ * C_];
// Scratch: feature map transposed to [B][C][W][H] for horizontal passes
__device__ float g_bufT[B_ * C_ * W_ * H_];

__device__ __forceinline__ ull pk2(float x) {
    ull r;
    asm("mov.b64 %0, {%1, %1};" : "=l"(r) : "f"(x));
    return r;
}
__device__ __forceinline__ void fma2(ull& d, ull a, ull b) {
    asm("fma.rn.f32x2 %0, %1, %2, %0;" : "+l"(d) : "l"(a), "l"(b));
}
__device__ __forceinline__ float2 unpk(ull v) {
    float2 f;
    asm("mov.b64 {%0, %1}, %2;" : "=f"(f.x), "=f"(f.y) : "l"(v));
    return f;
}
// Release/acquire cluster barrier (defaults of arrive/wait per PTX);
// all cross-CTA data moves via __stcg/__ldcg (L2-direct), so no extra
// GPU-scope fence is needed.
__device__ __forceinline__ void csync() {
    asm volatile("barrier.cluster.arrive.aligned;" ::: "memory");
    asm volatile("barrier.cluster.wait.aligned;" ::: "memory");
}

__global__ void transpose_weights(const float* __restrict__ w0,
                                  const float* __restrict__ w1,
                                  const float* __restrict__ w2,
                                  const float* __restrict__ w3) {
    const int per = C_ * C_ * K_;
    const int total = 4 * per;
    for (int idx = blockIdx.x * blockDim.x + threadIdx.x; idx < total;
         idx += gridDim.x * blockDim.x) {
        int p = idx / per;
        int r = idx - p * per;
        int ci = r / (K_ * C_);
        int k  = (r / C_) % K_;
        int co = r % C_;
        const float* src = (p == 0) ? w0 : (p == 1) ? w1 : (p == 2) ? w2 : w3;
        g_wtT[p][r] = src[(co * C_ + ci) * K_ + k];
    }
}

// ---------------------------------------------------------------------------
// Persistent kernel. Cluster of 4 CTAs = one batch (each CTA owns 32 co).
// Grid (4, 32): blockIdx.x = co-block, blockIdx.y = batch.
// ---------------------------------------------------------------------------
__global__ void __cluster_dims__(4, 1, 1) __launch_bounds__(256, 1)
scnn_persistent(float* __restrict__ buf) {
    extern __shared__ float smem[];
    float* ws = smem;                  // [ci][k][32] : 36864 floats
    float* pr = smem + C_ * K_ * 32;   // row/col buffer: 15360 floats

    const int b = blockIdx.y;
    const int co_base = blockIdx.x * 32;
    const int tid = threadIdx.x;
    const int copair = tid & 15;       // 0..15 -> co pair
    const int sgrp = tid >> 4;         // 0..15 -> spatial group
    const int co_l = copair * 2;

    float* bT = g_bufT;

    for (int pass = 0; pass < 4; pass++) {
        // ---- stage this pass's weight slice [ci][k][32co] into smem ----
        {
            const float* src = g_wtT[pass];
            for (int i = tid; i < C_ * K_ * 8; i += 256) {
                int cik = i >> 3;
                int g = (i & 7) * 4;
                float4 v = *(const float4*)(src + cik * C_ + co_base + g);
                *(float4*)(ws + cik * 32 + g) = v;
            }
        }

        if (pass == 0) {
            // zero smem pads for vertical layout (persist across steps)
            for (int i = tid; i < C_ * VLP; i += 256) {
                int wp = i % VLP;
                if (wp < PAD_ || wp >= PAD_ + W_) pr[i] = 0.f;
            }
        }

        if (pass == 2) {
            __syncthreads();
            // transpose own channel slice: buf[b][c][h][w] -> bT[b][c][w][h]
            for (int c = 0; c < 32; c++) {
                int ch = co_base + c;
                const float* srcp = buf + (size_t)(b * C_ + ch) * HW_;
                for (int i = tid; i < HW_ / 4; i += 256) {
                    float4 v = __ldcg((const float4*)srcp + i);
                    *(float4*)(pr + i * 4) = v;
                }
                __syncthreads();
                float* dstp = bT + (size_t)(b * C_ + ch) * HW_;
                for (int i = tid; i < HW_; i += 256) {
                    int w = i / H_, h = i - w * H_;
                    __stcg(dstp + i, pr[h * W_ + w]);
                }
                __syncthreads();
            }
            // zero smem pads for horizontal layout
            for (int i = tid; i < C_ * HLP; i += 256) {
                int hp = i % HLP;
                if (hp < PAD_ || hp >= PAD_ + H_) pr[i] = 0.f;
            }
            csync();
        }
        __syncthreads();  // weights (and pads) staged

        if (pass < 2) {
            // ================= vertical pass =================
            // 13 spatial groups of 8 w (104 >= 100), 32B-aligned pixel loads.
            const bool rev = (pass == 1);
            const int wbase = sgrp * 8;
            for (int s = 1; s < H_; s++) {
                const int cur = rev ? (H_ - 1 - s) : s;
                const int prev = rev ? (cur + 1) : (cur - 1);
                const float* rowg = buf + (size_t)b * C_ * HW_ + prev * W_;
                for (int i = tid; i < C_ * 25; i += 256) {
                    int ci = i / 25, q = i - ci * 25;
                    float4 v = __ldcg((const float4*)(rowg + ci * HW_) + q);
                    *(float4*)(pr + ci * VLP + PAD_ + q * 4) = v;
                }
                __syncthreads();

                if (sgrp < 13) {
                    ull acc[8];
#pragma unroll
                    for (int w = 0; w < 8; w++) acc[w] = 0ull;
                    for (int ci = 0; ci < C_; ci++) {
                        // padded origin: out pixel (wbase+w) reads padded
                        // inputs (wbase+w) .. (wbase+w+8)
                        const float* prp = pr + ci * VLP + wbase;
                        float4 q0 = *(const float4*)(prp);
                        float4 q1 = *(const float4*)(prp + 4);
                        float4 q2 = *(const float4*)(prp + 8);
                        float4 q3 = *(const float4*)(prp + 12);
                        ull pv[16];
                        pv[0]  = pk2(q0.x); pv[1]  = pk2(q0.y);
                        pv[2]  = pk2(q0.z); pv[3]  = pk2(q0.w);
                        pv[4]  = pk2(q1.x); pv[5]  = pk2(q1.y);
                        pv[6]  = pk2(q1.z); pv[7]  = pk2(q1.w);
                        pv[8]  = pk2(q2.x); pv[9]  = pk2(q2.y);
                        pv[10] = pk2(q2.z); pv[11] = pk2(q2.w);
                        pv[12] = pk2(q3.x); pv[13] = pk2(q3.y);
                        pv[14] = pk2(q3.z); pv[15] = pk2(q3.w);
                        const float* wr = ws + ci * (K_ * 32) + co_l;
#pragma unroll
                        for (int k = 0; k < K_; k++) {
                            ull wv = *(const ull*)(wr + k * 32);
#pragma unroll
                            for (int w = 0; w < 8; w++)
                                fma2(acc[w], wv, pv[k + w]);
                        }
                    }
                    // vectorized += relu epilogue (two channel rows)
                    float a0[8], a1[8];
#pragma unroll
                    for (int w = 0; w < 8; w++) {
                        float2 v = unpk(acc[w]);
                        a0[w] = fmaxf(v.x, 0.f);
                        a1[w] = fmaxf(v.y, 0.f);
                    }
                    float* o0 = buf + ((size_t)(b * C_ + co_base + co_l) * H_ + cur) * W_ + wbase;
                    float* o1 = o0 + HW_;
                    float4 t;
                    t = __ldcg((float4*)o0);
                    t.x += a0[0]; t.y += a0[1]; t.z += a0[2]; t.w += a0[3];
                    __stcg((float4*)o0, t);
                    t = __ldcg((float4*)o1);
                    t.x += a1[0]; t.y += a1[1]; t.z += a1[2]; t.w += a1[3];
                    __stcg((float4*)o1, t);
                    if (wbase + 8 <= W_) {  // sgrp < 12: second half valid
                        t = __ldcg((float4*)(o0 + 4));
                        t.x += a0[4]; t.y += a0[5]; t.z += a0[6]; t.w += a0[7];
                        __stcg((float4*)(o0 + 4), t);
                        t = __ldcg((float4*)(o1 + 4));
                        t.x += a1[4]; t.y += a1[5]; t.z += a1[6]; t.w += a1[7];
                        __stcg((float4*)(o1 + 4), t);
                    }
                }
                csync();
            }
        } else {
            // ================= horizontal pass (on bT, [b][c][w][h]) =========
            // 9 spatial groups of 4 h (36), 16B-aligned pixel loads.
            const bool rev = (pass == 3);
            const int hbase = sgrp * 4;
            for (int s = 1; s < W_; s++) {
                const int cur = rev ? (W_ - 1 - s) : s;
                const int prev = rev ? (cur + 1) : (cur - 1);
                const float* colg = bT + (size_t)b * C_ * HW_ + prev * H_;
                for (int i = tid; i < C_ * 9; i += 256) {
                    int ci = i / 9, q = i - ci * 9;
                    float4 v = __ldcg((const float4*)(colg + ci * HW_) + q);
                    *(float4*)(pr + ci * HLP + PAD_ + q * 4) = v;
                }
                __syncthreads();

                if (sgrp < 9) {
                    ull acc[4];
                    acc[0] = acc[1] = acc[2] = acc[3] = 0ull;
                    for (int ci = 0; ci < C_; ci++) {
                        const float* prp = pr + ci * HLP + hbase;
                        float4 q0 = *(const float4*)(prp);
                        float4 q1 = *(const float4*)(prp + 4);
                        float4 q2 = *(const float4*)(prp + 8);
                        ull pv[12];
                        pv[0]  = pk2(q0.x); pv[1]  = pk2(q0.y);
                        pv[2]  = pk2(q0.z); pv[3]  = pk2(q0.w);
                        pv[4]  = pk2(q1.x); pv[5]  = pk2(q1.y);
                        pv[6]  = pk2(q1.z); pv[7]  = pk2(q1.w);
                        pv[8]  = pk2(q2.x); pv[9]  = pk2(q2.y);
                        pv[10] = pk2(q2.z); pv[11] = pk2(q2.w);
                        const float* wr = ws + ci * (K_ * 32) + co_l;
#pragma unroll
                        for (int k = 0; k < K_; k++) {
                            ull wv = *(const ull*)(wr + k * 32);
#pragma unroll
                            for (int h = 0; h < 4; h++)
                                fma2(acc[h], wv, pv[k + h]);
                        }
                    }
                    float a0[4], a1[4];
#pragma unroll
                    for (int h = 0; h < 4; h++) {
                        float2 v = unpk(acc[h]);
                        a0[h] = fmaxf(v.x, 0.f);
                        a1[h] = fmaxf(v.y, 0.f);
                    }
                    float* o0 = bT + ((size_t)(b * C_ + co_base + co_l) * W_ + cur) * H_ + hbase;
                    float* o1 = o0 + HW_;
                    float4 t;
                    t = __ldcg((float4*)o0);
                    t.x += a0[0]; t.y += a0[1]; t.z += a0[2]; t.w += a0[3];
                    __stcg((float4*)o0, t);
                    t = __ldcg((float4*)o1);
                    t.x += a1[0]; t.y += a1[1]; t.z += a1[2]; t.w += a1[3];
                    __stcg((float4*)o1, t);
                }
                csync();
            }
        }
        csync();  // end of pass

        if (pass == 3) {
            // transpose back: bT[b][c][w][h] -> buf[b][c][h][w]
            for (int c = 0; c < 32; c++) {
                int ch = co_base + c;
                const float* srcp = bT + (size_t)(b * C_ + ch) * HW_;
                for (int i = tid; i < HW_ / 4; i += 256) {
                    float4 v = __ldcg((const float4*)srcp + i);
                    *(float4*)(pr + i * 4) = v;
                }
                __syncthreads();
                float* dstp = buf + (size_t)(b * C_ + ch) * HW_;
                for (int i = tid; i < HW_; i += 256) {
                    int h = i / W_, w = i - h * W_;
                    __stcg(dstp + i, pr[w * H_ + h]);
                }
                __syncthreads();
            }
        }
    }
}

extern "C" void kernel_launch(void* const* d_in, const int* in_sizes, int n_in,
                              void* d_out, int out_size) {
    const float* x    = (const float*)d_in[0];
    const float* w_ud = (const float*)d_in[1];
    const float* w_du = (const float*)d_in[2];
    const float* w_lr = (const float*)d_in[3];
    const float* w_rl = (const float*)d_in[4];
    float* buf = (float*)d_out;

    size_t bytes = (size_t)B_ * C_ * HW_ * sizeof(float);
    cudaMemcpyAsync(buf, x, bytes, cudaMemcpyDeviceToDevice, 0);

    transpose_weights<<<288, 256>>>(w_ud, w_du, w_lr, w_rl);

    const int smem_bytes = (C_ * K_ * 32 + C_ * VLP) * sizeof(float);  // 208896
    cudaFuncSetAttribute(scnn_persistent,
                         cudaFuncAttributeMaxDynamicSharedMemorySize, smem_bytes);

    dim3 grid(4, B_);
    scnn_persistent<<<grid, 256, smem_bytes>>>(buf);
}